// round 2
// baseline (speedup 1.0000x reference)
#include <cuda_runtime.h>
#include <cuda_bf16.h>
#include <math.h>

// Problem constants
#define BATCH 4
#define SEQ   2048
#define EMB   1024
#define HEADS 16
#define HDIM  64
#define QKVN  (3 * EMB)          // 3072
#define ROWS  (BATCH * SEQ)      // 8192

// ---------------------------------------------------------------------------
// Scratch (no cudaMalloc allowed) — head-major Q/K/V + attention output
// ---------------------------------------------------------------------------
__device__ float g_q[BATCH * HEADS * SEQ * HDIM];
__device__ float g_k[BATCH * HEADS * SEQ * HDIM];
__device__ float g_v[BATCH * HEADS * SEQ * HDIM];
__device__ float g_attn[ROWS * EMB];   // [B,N,H*D] — ready for out-proj GEMM

// ---------------------------------------------------------------------------
// Kernel 1: QKV GEMM.  y[m][j] = sum_k x[m][k]*W[j][k] + b[j]
// x: [8192,1024] row-major, W: [3072,1024] row-major (both K-major => "NT" GEMM)
// 128x128 block tile, K-step 16, 256 threads, 8x8 per-thread micro-tile.
// Epilogue scatters into g_q/g_k/g_v as [B,H,N,D].
// ---------------------------------------------------------------------------
__global__ __launch_bounds__(256) void qkv_gemm_kernel(
    const float* __restrict__ x,
    const float* __restrict__ w,
    const float* __restrict__ bias)
{
    __shared__ __align__(16) float As[16 * 132];  // [kk][m], pad 132
    __shared__ __align__(16) float Bs[16 * 132];  // [kk][j]

    const int m0 = blockIdx.x * 128;
    const int j0 = blockIdx.y * 128;
    const int tid = threadIdx.x;
    const int ty = tid >> 4;       // 0..15
    const int tx = tid & 15;       // 0..15

    float acc[8][8];
#pragma unroll
    for (int i = 0; i < 8; i++)
#pragma unroll
        for (int j = 0; j < 8; j++) acc[i][j] = 0.0f;

    for (int k0 = 0; k0 < EMB; k0 += 16) {
        // Load A tile (128 rows x 16 k) and B tile, transposed into smem.
#pragma unroll
        for (int it = 0; it < 2; it++) {
            int f   = tid + it * 256;     // 0..511
            int row = f >> 2;             // 0..127
            int c4  = f & 3;              // 0..3
            float4 va = *(const float4*)(x + (size_t)(m0 + row) * EMB + k0 + c4 * 4);
            As[(c4 * 4 + 0) * 132 + row] = va.x;
            As[(c4 * 4 + 1) * 132 + row] = va.y;
            As[(c4 * 4 + 2) * 132 + row] = va.z;
            As[(c4 * 4 + 3) * 132 + row] = va.w;
            float4 vb = *(const float4*)(w + (size_t)(j0 + row) * EMB + k0 + c4 * 4);
            Bs[(c4 * 4 + 0) * 132 + row] = vb.x;
            Bs[(c4 * 4 + 1) * 132 + row] = vb.y;
            Bs[(c4 * 4 + 2) * 132 + row] = vb.z;
            Bs[(c4 * 4 + 3) * 132 + row] = vb.w;
        }
        __syncthreads();

#pragma unroll
        for (int kk = 0; kk < 16; kk++) {
            float a[8], b[8];
            *(float4*)(a)     = *(const float4*)&As[kk * 132 + ty * 8];
            *(float4*)(a + 4) = *(const float4*)&As[kk * 132 + ty * 8 + 4];
            *(float4*)(b)     = *(const float4*)&Bs[kk * 132 + tx * 8];
            *(float4*)(b + 4) = *(const float4*)&Bs[kk * 132 + tx * 8 + 4];
#pragma unroll
            for (int i = 0; i < 8; i++)
#pragma unroll
                for (int j = 0; j < 8; j++)
                    acc[i][j] = fmaf(a[i], b[j], acc[i][j]);
        }
        __syncthreads();
    }

    // Epilogue: add bias, scatter to q/k/v [B,H,N,D]
#pragma unroll
    for (int i = 0; i < 8; i++) {
        int m = m0 + ty * 8 + i;
        int b = m >> 11;          // /2048
        int n = m & (SEQ - 1);
#pragma unroll
        for (int j = 0; j < 8; j++) {
            int jj  = j0 + tx * 8 + j;
            float v = acc[i][j] + bias[jj];
            int which = jj >> 10;       // 0:q 1:k 2:v
            int rem   = jj & 1023;
            int h     = rem >> 6;
            int d     = rem & 63;
            float* dst = (which == 0) ? g_q : (which == 1) ? g_k : g_v;
            dst[((((size_t)b * HEADS + h) * SEQ) + n) * HDIM + d] = v;
        }
    }
}

// ---------------------------------------------------------------------------
// Kernel 2: Flash attention.  One CTA = (b, h, 64-query tile).
// Streams K/V in 32-key tiles with online softmax (static smem <= 48KB,
// no cudaFuncSetAttribute needed).
// Thread grid 16x16: thread (ty,tx) owns q-rows ty*4..+4.
//   S phase: cols tx*2..+2 of the 32-key tile.
//   O phase: cols tx*4..+4 of the 64-dim output.
// Row reductions across the 16 tx lanes via shfl.xor (contiguous half-warp).
// Output -> g_attn[b][n][h*64+d].
// ---------------------------------------------------------------------------
#define KT 32

__global__ __launch_bounds__(256) void attn_kernel()
{
    __shared__ __align__(16) float Qs[64 * 64];   // broadcast reads: no pad
    __shared__ __align__(16) float Ks[KT * 65];   // pad kills transpose conflicts
    __shared__ __align__(16) float Vs[KT * 64];
    __shared__ __align__(16) float Ps[64 * KT];

    const int tid = threadIdx.x;
    const int ty  = tid >> 4;
    const int tx  = tid & 15;
    const int q0  = blockIdx.x * 64;
    const int h   = blockIdx.y;
    const int b   = blockIdx.z;
    const float scale = 0.125f;       // 1/sqrt(64)

    const size_t head_off = (((size_t)b * HEADS + h) * SEQ) * HDIM;
    const float* qg = g_q + head_off;
    const float* kg = g_k + head_off;
    const float* vg = g_v + head_off;

    // Load Q tile (64x64): 4 float4 per thread
#pragma unroll
    for (int it = 0; it < 4; it++) {
        int f   = tid + it * 256;      // 0..1023
        int row = f >> 4;
        int c4  = f & 15;
        float4 v = *(const float4*)(qg + (size_t)(q0 + row) * HDIM + c4 * 4);
        Qs[row * 64 + c4 * 4 + 0] = v.x;
        Qs[row * 64 + c4 * 4 + 1] = v.y;
        Qs[row * 64 + c4 * 4 + 2] = v.z;
        Qs[row * 64 + c4 * 4 + 3] = v.w;
    }

    float o[4][4];
    float l[4], mx[4];
#pragma unroll
    for (int i = 0; i < 4; i++) {
        l[i] = 0.0f; mx[i] = -1e30f;
#pragma unroll
        for (int j = 0; j < 4; j++) o[i][j] = 0.0f;
    }

    for (int kt = 0; kt < SEQ; kt += KT) {
        __syncthreads();   // previous iteration's smem reads complete
        // Load K (padded 65) and V tiles: KT*64 floats = 512 float4 each,
        // 2 float4 per thread per tile.
#pragma unroll
        for (int it = 0; it < 2; it++) {
            int f   = tid + it * 256;      // 0..511
            int row = f >> 4;              // 0..31
            int c4  = f & 15;
            float4 kv = *(const float4*)(kg + (size_t)(kt + row) * HDIM + c4 * 4);
            Ks[row * 65 + c4 * 4 + 0] = kv.x;
            Ks[row * 65 + c4 * 4 + 1] = kv.y;
            Ks[row * 65 + c4 * 4 + 2] = kv.z;
            Ks[row * 65 + c4 * 4 + 3] = kv.w;
            float4 vv = *(const float4*)(vg + (size_t)(kt + row) * HDIM + c4 * 4);
            Vs[row * 64 + c4 * 4 + 0] = vv.x;
            Vs[row * 64 + c4 * 4 + 1] = vv.y;
            Vs[row * 64 + c4 * 4 + 2] = vv.z;
            Vs[row * 64 + c4 * 4 + 3] = vv.w;
        }
        __syncthreads();   // tiles ready (covers Q on first iter)

        // S = Q @ K^T : each thread 4 rows x 2 key-cols
        float s[4][2];
#pragma unroll
        for (int i = 0; i < 4; i++) { s[i][0] = 0.0f; s[i][1] = 0.0f; }

#pragma unroll 8
        for (int d = 0; d < 64; d++) {
            float qa[4], kb[2];
#pragma unroll
            for (int i = 0; i < 4; i++) qa[i] = Qs[(ty * 4 + i) * 64 + d];
            kb[0] = Ks[(tx * 2 + 0) * 65 + d];
            kb[1] = Ks[(tx * 2 + 1) * 65 + d];
#pragma unroll
            for (int i = 0; i < 4; i++) {
                s[i][0] = fmaf(qa[i], kb[0], s[i][0]);
                s[i][1] = fmaf(qa[i], kb[1], s[i][1]);
            }
        }

        // Online softmax per q-row (reduce across 16 tx lanes = half-warp)
#pragma unroll
        for (int i = 0; i < 4; i++) {
            s[i][0] *= scale;
            s[i][1] *= scale;
            float tm = fmaxf(s[i][0], s[i][1]);
#pragma unroll
            for (int off = 8; off >= 1; off >>= 1)
                tm = fmaxf(tm, __shfl_xor_sync(0xffffffffu, tm, off));
            float newm = fmaxf(mx[i], tm);
            float corr = __expf(mx[i] - newm);
            mx[i] = newm;
            s[i][0] = __expf(s[i][0] - newm);
            s[i][1] = __expf(s[i][1] - newm);
            float rs = s[i][0] + s[i][1];
#pragma unroll
            for (int off = 8; off >= 1; off >>= 1)
                rs += __shfl_xor_sync(0xffffffffu, rs, off);
            l[i] = l[i] * corr + rs;
#pragma unroll
            for (int j = 0; j < 4; j++) o[i][j] *= corr;
        }

        // P to shared
#pragma unroll
        for (int i = 0; i < 4; i++) {
            Ps[(ty * 4 + i) * KT + tx * 2 + 0] = s[i][0];
            Ps[(ty * 4 + i) * KT + tx * 2 + 1] = s[i][1];
        }
        __syncthreads();

        // O += P @ V
#pragma unroll 8
        for (int k = 0; k < KT; k++) {
            float pa[4], vb[4];
#pragma unroll
            for (int i = 0; i < 4; i++) pa[i] = Ps[(ty * 4 + i) * KT + k];
#pragma unroll
            for (int j = 0; j < 4; j++) vb[j] = Vs[k * 64 + tx * 4 + j];
#pragma unroll
            for (int i = 0; i < 4; i++)
#pragma unroll
                for (int j = 0; j < 4; j++)
                    o[i][j] = fmaf(pa[i], vb[j], o[i][j]);
        }
    }

    // Epilogue: normalize, write [B,N,H*D]
#pragma unroll
    for (int i = 0; i < 4; i++) {
        int q = q0 + ty * 4 + i;
        float inv_l = 1.0f / l[i];
        size_t base = ((size_t)b * SEQ + q) * EMB + h * HDIM;
#pragma unroll
        for (int j = 0; j < 4; j++)
            g_attn[base + tx * 4 + j] = o[i][j] * inv_l;
    }
}

// ---------------------------------------------------------------------------
// Kernel 3: output projection GEMM. out[m][j] = sum_k attn[m][k]*Wo[j][k]+bo[j]
// Same scheme as kernel 1, 1024 output cols.
// ---------------------------------------------------------------------------
__global__ __launch_bounds__(256) void proj_gemm_kernel(
    const float* __restrict__ w,
    const float* __restrict__ bias,
    float* __restrict__ out)
{
    __shared__ __align__(16) float As[16 * 132];
    __shared__ __align__(16) float Bs[16 * 132];

    const int m0 = blockIdx.x * 128;
    const int j0 = blockIdx.y * 128;
    const int tid = threadIdx.x;
    const int ty = tid >> 4;
    const int tx = tid & 15;

    float acc[8][8];
#pragma unroll
    for (int i = 0; i < 8; i++)
#pragma unroll
        for (int j = 0; j < 8; j++) acc[i][j] = 0.0f;

    for (int k0 = 0; k0 < EMB; k0 += 16) {
#pragma unroll
        for (int it = 0; it < 2; it++) {
            int f   = tid + it * 256;
            int row = f >> 2;
            int c4  = f & 3;
            float4 va = *(const float4*)(g_attn + (size_t)(m0 + row) * EMB + k0 + c4 * 4);
            As[(c4 * 4 + 0) * 132 + row] = va.x;
            As[(c4 * 4 + 1) * 132 + row] = va.y;
            As[(c4 * 4 + 2) * 132 + row] = va.z;
            As[(c4 * 4 + 3) * 132 + row] = va.w;
            float4 vb = *(const float4*)(w + (size_t)(j0 + row) * EMB + k0 + c4 * 4);
            Bs[(c4 * 4 + 0) * 132 + row] = vb.x;
            Bs[(c4 * 4 + 1) * 132 + row] = vb.y;
            Bs[(c4 * 4 + 2) * 132 + row] = vb.z;
            Bs[(c4 * 4 + 3) * 132 + row] = vb.w;
        }
        __syncthreads();

#pragma unroll
        for (int kk = 0; kk < 16; kk++) {
            float a[8], b[8];
            *(float4*)(a)     = *(const float4*)&As[kk * 132 + ty * 8];
            *(float4*)(a + 4) = *(const float4*)&As[kk * 132 + ty * 8 + 4];
            *(float4*)(b)     = *(const float4*)&Bs[kk * 132 + tx * 8];
            *(float4*)(b + 4) = *(const float4*)&Bs[kk * 132 + tx * 8 + 4];
#pragma unroll
            for (int i = 0; i < 8; i++)
#pragma unroll
                for (int j = 0; j < 8; j++)
                    acc[i][j] = fmaf(a[i], b[j], acc[i][j]);
        }
        __syncthreads();
    }

#pragma unroll
    for (int i = 0; i < 8; i++) {
        size_t m = m0 + ty * 8 + i;
#pragma unroll
        for (int j = 0; j < 8; j++) {
            int jj = j0 + tx * 8 + j;
            out[m * EMB + jj] = acc[i][j] + bias[jj];
        }
    }
}

// ---------------------------------------------------------------------------
// Launch
// ---------------------------------------------------------------------------
extern "C" void kernel_launch(void* const* d_in, const int* in_sizes, int n_in,
                              void* d_out, int out_size)
{
    const float* x     = (const float*)d_in[0];
    const float* qkv_w = (const float*)d_in[1];
    const float* qkv_b = (const float*)d_in[2];
    const float* out_w = (const float*)d_in[3];
    const float* out_b = (const float*)d_in[4];
    float* out = (float*)d_out;

    dim3 g1(ROWS / 128, QKVN / 128);     // 64 x 24
    qkv_gemm_kernel<<<g1, 256>>>(x, qkv_w, qkv_b);

    dim3 g2(SEQ / 64, HEADS, BATCH);     // 32 x 16 x 4
    attn_kernel<<<g2, 256>>>();

    dim3 g3(ROWS / 128, EMB / 128);      // 64 x 8
    proj_gemm_kernel<<<g3, 256>>>(out_w, out_b, out);
}

// round 3
// speedup vs baseline: 3.1089x; 3.1089x over previous
#include <cuda_runtime.h>
#include <cuda_bf16.h>
#include <math.h>

// Problem constants
#define BATCH 4
#define SEQ   2048
#define EMB   1024
#define HEADS 16
#define HDIM  64
#define QKVN  (3 * EMB)          // 3072
#define ROWS  (BATCH * SEQ)      // 8192

// ---------------------------------------------------------------------------
// Scratch — head-major Q/K/V + attention output
// ---------------------------------------------------------------------------
__device__ float g_q[BATCH * HEADS * SEQ * HDIM];
__device__ float g_k[BATCH * HEADS * SEQ * HDIM];
__device__ float g_v[BATCH * HEADS * SEQ * HDIM];
__device__ float g_attn[ROWS * EMB];   // [B,N,H*D]

// ---------------------------------------------------------------------------
// tf32 helpers
// ---------------------------------------------------------------------------
__device__ __forceinline__ unsigned f2tf(float f) {
    unsigned u;
    asm("cvt.rna.tf32.f32 %0, %1;" : "=r"(u) : "f"(f));
    return u;
}

__device__ __forceinline__ void mma_tf32(float d[4], const unsigned a[4],
                                         const unsigned b[2]) {
    asm volatile(
        "mma.sync.aligned.m16n8k8.row.col.f32.tf32.tf32.f32 "
        "{%0,%1,%2,%3}, {%4,%5,%6,%7}, {%8,%9}, {%0,%1,%2,%3};"
        : "+f"(d[0]), "+f"(d[1]), "+f"(d[2]), "+f"(d[3])
        : "r"(a[0]), "r"(a[1]), "r"(a[2]), "r"(a[3]),
          "r"(b[0]), "r"(b[1]));
}

// ---------------------------------------------------------------------------
// Shared GEMM mainloop: C[128x128] = A[m0.., 1024] * B[j0.., 1024]^T
// (both row-major, K-contiguous). 256 threads = 8 warps, warp tile 32x64.
// acc[mi][nf][slot]: warp rows wm*32+mi*16+{g,g+8}, cols wn*64+nf*8+2*l4+{0,1}
// slot = rowsel*2 + colsel.
// ---------------------------------------------------------------------------
#define SPAD 20   // smem row stride (conflict-free fragment reads)

__device__ __forceinline__ void gemm_mainloop(
    const float* __restrict__ Ag, const float* __restrict__ Bg,
    int m0, int j0, unsigned* As, unsigned* Bs, float acc[2][8][4])
{
    const int tid  = threadIdx.x;
    const int lane = tid & 31;
    const int w    = tid >> 5;
    const int g    = lane >> 2;
    const int l4   = lane & 3;
    const int wm   = w >> 1;
    const int wn   = w & 1;

    const int r0 = tid >> 2;          // 0..63
    const int c0 = (tid & 3) * 4;     // 0,4,8,12

#pragma unroll
    for (int mi = 0; mi < 2; mi++)
#pragma unroll
        for (int nf = 0; nf < 8; nf++)
#pragma unroll
            for (int s = 0; s < 4; s++) acc[mi][nf][s] = 0.0f;

    // Prefetch slab 0
    float4 pa0 = *(const float4*)(Ag + (size_t)(m0 + r0) * EMB + c0);
    float4 pa1 = *(const float4*)(Ag + (size_t)(m0 + r0 + 64) * EMB + c0);
    float4 pb0 = *(const float4*)(Bg + (size_t)(j0 + r0) * EMB + c0);
    float4 pb1 = *(const float4*)(Bg + (size_t)(j0 + r0 + 64) * EMB + c0);

    for (int k0 = 0; k0 < EMB; k0 += 16) {
        // Store prefetched slab (convert to tf32 bits)
        unsigned* a0p = As + r0 * SPAD + c0;
        a0p[0] = f2tf(pa0.x); a0p[1] = f2tf(pa0.y);
        a0p[2] = f2tf(pa0.z); a0p[3] = f2tf(pa0.w);
        unsigned* a1p = As + (r0 + 64) * SPAD + c0;
        a1p[0] = f2tf(pa1.x); a1p[1] = f2tf(pa1.y);
        a1p[2] = f2tf(pa1.z); a1p[3] = f2tf(pa1.w);
        unsigned* b0p = Bs + r0 * SPAD + c0;
        b0p[0] = f2tf(pb0.x); b0p[1] = f2tf(pb0.y);
        b0p[2] = f2tf(pb0.z); b0p[3] = f2tf(pb0.w);
        unsigned* b1p = Bs + (r0 + 64) * SPAD + c0;
        b1p[0] = f2tf(pb1.x); b1p[1] = f2tf(pb1.y);
        b1p[2] = f2tf(pb1.z); b1p[3] = f2tf(pb1.w);
        __syncthreads();

        if (k0 + 16 < EMB) {
            pa0 = *(const float4*)(Ag + (size_t)(m0 + r0) * EMB + k0 + 16 + c0);
            pa1 = *(const float4*)(Ag + (size_t)(m0 + r0 + 64) * EMB + k0 + 16 + c0);
            pb0 = *(const float4*)(Bg + (size_t)(j0 + r0) * EMB + k0 + 16 + c0);
            pb1 = *(const float4*)(Bg + (size_t)(j0 + r0 + 64) * EMB + k0 + 16 + c0);
        }

#pragma unroll
        for (int ks = 0; ks < 2; ks++) {
            const int kk = ks * 8;
            unsigned a[2][4];
#pragma unroll
            for (int mi = 0; mi < 2; mi++) {
                int mr = wm * 32 + mi * 16 + g;
                a[mi][0] = As[mr * SPAD + kk + l4];
                a[mi][1] = As[(mr + 8) * SPAD + kk + l4];
                a[mi][2] = As[mr * SPAD + kk + l4 + 4];
                a[mi][3] = As[(mr + 8) * SPAD + kk + l4 + 4];
            }
#pragma unroll
            for (int nf = 0; nf < 8; nf++) {
                int nr = wn * 64 + nf * 8 + g;
                unsigned b[2];
                b[0] = Bs[nr * SPAD + kk + l4];
                b[1] = Bs[nr * SPAD + kk + l4 + 4];
                mma_tf32(acc[0][nf], a[0], b);
                mma_tf32(acc[1][nf], a[1], b);
            }
        }
        __syncthreads();
    }
}

// ---------------------------------------------------------------------------
// Kernel 1: QKV GEMM + scatter into head-major g_q/g_k/g_v
// ---------------------------------------------------------------------------
__global__ __launch_bounds__(256) void qkv_gemm_kernel(
    const float* __restrict__ x,
    const float* __restrict__ w,
    const float* __restrict__ bias)
{
    __shared__ unsigned As[128 * SPAD];
    __shared__ unsigned Bs[128 * SPAD];
    float acc[2][8][4];
    const int m0 = blockIdx.x * 128;
    const int j0 = blockIdx.y * 128;
    gemm_mainloop(x, w, m0, j0, As, Bs, acc);

    const int lane = threadIdx.x & 31;
    const int wrp  = threadIdx.x >> 5;
    const int g = lane >> 2, l4 = lane & 3;
    const int wm = wrp >> 1, wn = wrp & 1;

#pragma unroll
    for (int mi = 0; mi < 2; mi++)
#pragma unroll
        for (int rr = 0; rr < 2; rr++) {
            int m = m0 + wm * 32 + mi * 16 + g + rr * 8;
            int b = m >> 11;
            int n = m & (SEQ - 1);
#pragma unroll
            for (int nf = 0; nf < 8; nf++)
#pragma unroll
                for (int cc = 0; cc < 2; cc++) {
                    int jj = j0 + wn * 64 + nf * 8 + 2 * l4 + cc;
                    float v = acc[mi][nf][rr * 2 + cc] + bias[jj];
                    int which = jj >> 10;
                    int rem = jj & 1023;
                    int h = rem >> 6, d = rem & 63;
                    float* dst = (which == 0) ? g_q : (which == 1) ? g_k : g_v;
                    dst[((((size_t)b * HEADS + h) * SEQ) + n) * HDIM + d] = v;
                }
        }
}

// ---------------------------------------------------------------------------
// Kernel 3: out-proj GEMM
// ---------------------------------------------------------------------------
__global__ __launch_bounds__(256) void proj_gemm_kernel(
    const float* __restrict__ w,
    const float* __restrict__ bias,
    float* __restrict__ out)
{
    __shared__ unsigned As[128 * SPAD];
    __shared__ unsigned Bs[128 * SPAD];
    float acc[2][8][4];
    const int m0 = blockIdx.x * 128;
    const int j0 = blockIdx.y * 128;
    gemm_mainloop(g_attn, w, m0, j0, As, Bs, acc);

    const int lane = threadIdx.x & 31;
    const int wrp  = threadIdx.x >> 5;
    const int g = lane >> 2, l4 = lane & 3;
    const int wm = wrp >> 1, wn = wrp & 1;

#pragma unroll
    for (int mi = 0; mi < 2; mi++)
#pragma unroll
        for (int rr = 0; rr < 2; rr++) {
            size_t m = m0 + wm * 32 + mi * 16 + g + rr * 8;
#pragma unroll
            for (int nf = 0; nf < 8; nf++)
#pragma unroll
                for (int cc = 0; cc < 2; cc++) {
                    int jj = j0 + wn * 64 + nf * 8 + 2 * l4 + cc;
                    out[m * EMB + jj] = acc[mi][nf][rr * 2 + cc] + bias[jj];
                }
        }
}

// ---------------------------------------------------------------------------
// Kernel 2: flash attention with tf32 tensor cores.
// CTA = 128 threads (4 warps), 64-query tile; warp w owns q rows w*16..+16.
// Q held persistently in A-fragments (scaled by 1/8). Key tiles of 64:
// K staged in Ks (stride 76), V in Vs (stride 72). After S-phase, Ks region is
// reused for P (tf32 bits). Layouts chosen for conflict-free fragment reads.
// ---------------------------------------------------------------------------
#define KSTRIDE 76
#define VSTRIDE 72

__global__ __launch_bounds__(128) void attn_kernel()
{
    __shared__ unsigned Ks[64 * KSTRIDE];   // K tile, then P tile
    __shared__ unsigned Vs[64 * VSTRIDE];

    const int tid  = threadIdx.x;
    const int lane = tid & 31;
    const int w    = tid >> 5;
    const int g    = lane >> 2;
    const int l4   = lane & 3;
    const int q0   = blockIdx.x * 64;
    const int h    = blockIdx.y;
    const int bb   = blockIdx.z;

    const size_t head_off = (((size_t)bb * HEADS + h) * SEQ) * HDIM;
    const float* qg = g_q + head_off;
    const float* kg = g_k + head_off;
    const float* vg = g_v + head_off;

    // Persistent Q fragments (scale 1/sqrt(64) folded in)
    const int qbase = q0 + w * 16;
    unsigned qa[8][4];
    {
        const float* qr0 = qg + (size_t)(qbase + g) * HDIM;
        const float* qr1 = qg + (size_t)(qbase + g + 8) * HDIM;
#pragma unroll
        for (int kf = 0; kf < 8; kf++) {
            qa[kf][0] = f2tf(qr0[kf * 8 + l4] * 0.125f);
            qa[kf][1] = f2tf(qr1[kf * 8 + l4] * 0.125f);
            qa[kf][2] = f2tf(qr0[kf * 8 + l4 + 4] * 0.125f);
            qa[kf][3] = f2tf(qr1[kf * 8 + l4 + 4] * 0.125f);
        }
    }

    float oacc[8][4];
#pragma unroll
    for (int nf = 0; nf < 8; nf++)
#pragma unroll
        for (int s = 0; s < 4; s++) oacc[nf][s] = 0.0f;
    float mx0 = -1e30f, mx1 = -1e30f, l0 = 0.0f, l1 = 0.0f;

    for (int kt = 0; kt < SEQ; kt += 64) {
        __syncthreads();   // all warps done with Ks(P) / Vs of previous tile

        // Load K and V tiles (64x64), convert to tf32 bits
#pragma unroll
        for (int it = 0; it < 8; it++) {
            int f   = tid + it * 128;
            int row = f >> 4;
            int c4  = (f & 15) * 4;
            float4 kv = *(const float4*)(kg + (size_t)(kt + row) * HDIM + c4);
            unsigned* kp = Ks + row * KSTRIDE + c4;
            kp[0] = f2tf(kv.x); kp[1] = f2tf(kv.y);
            kp[2] = f2tf(kv.z); kp[3] = f2tf(kv.w);
            float4 vv = *(const float4*)(vg + (size_t)(kt + row) * HDIM + c4);
            unsigned* vp = Vs + row * VSTRIDE + c4;
            vp[0] = f2tf(vv.x); vp[1] = f2tf(vv.y);
            vp[2] = f2tf(vv.z); vp[3] = f2tf(vv.w);
        }
        __syncthreads();

        // S = (Q/8) @ K^T : warp computes 16x64
        float sacc[8][4];
#pragma unroll
        for (int nf = 0; nf < 8; nf++)
#pragma unroll
            for (int s = 0; s < 4; s++) sacc[nf][s] = 0.0f;

#pragma unroll
        for (int nf = 0; nf < 8; nf++) {
            const unsigned* kr = Ks + (nf * 8 + g) * KSTRIDE;
#pragma unroll
            for (int kf = 0; kf < 8; kf++) {
                unsigned b[2];
                b[0] = kr[kf * 8 + l4];
                b[1] = kr[kf * 8 + l4 + 4];
                mma_tf32(sacc[nf], qa[kf], b);
            }
        }

        // Online softmax for this tile (rows g and g+8 of warp's 16)
        float tm0 = -1e30f, tm1 = -1e30f;
#pragma unroll
        for (int nf = 0; nf < 8; nf++) {
            tm0 = fmaxf(tm0, fmaxf(sacc[nf][0], sacc[nf][1]));
            tm1 = fmaxf(tm1, fmaxf(sacc[nf][2], sacc[nf][3]));
        }
        tm0 = fmaxf(tm0, __shfl_xor_sync(0xffffffffu, tm0, 1));
        tm0 = fmaxf(tm0, __shfl_xor_sync(0xffffffffu, tm0, 2));
        tm1 = fmaxf(tm1, __shfl_xor_sync(0xffffffffu, tm1, 1));
        tm1 = fmaxf(tm1, __shfl_xor_sync(0xffffffffu, tm1, 2));

        float nm0 = fmaxf(mx0, tm0), nm1 = fmaxf(mx1, tm1);
        float c0 = __expf(mx0 - nm0), c1 = __expf(mx1 - nm1);
        mx0 = nm0; mx1 = nm1;

        float rs0 = 0.0f, rs1 = 0.0f;
#pragma unroll
        for (int nf = 0; nf < 8; nf++) {
            sacc[nf][0] = __expf(sacc[nf][0] - nm0); rs0 += sacc[nf][0];
            sacc[nf][1] = __expf(sacc[nf][1] - nm0); rs0 += sacc[nf][1];
            sacc[nf][2] = __expf(sacc[nf][2] - nm1); rs1 += sacc[nf][2];
            sacc[nf][3] = __expf(sacc[nf][3] - nm1); rs1 += sacc[nf][3];
        }
        rs0 += __shfl_xor_sync(0xffffffffu, rs0, 1);
        rs0 += __shfl_xor_sync(0xffffffffu, rs0, 2);
        rs1 += __shfl_xor_sync(0xffffffffu, rs1, 1);
        rs1 += __shfl_xor_sync(0xffffffffu, rs1, 2);
        l0 = l0 * c0 + rs0;
        l1 = l1 * c1 + rs1;
#pragma unroll
        for (int nf = 0; nf < 8; nf++) {
            oacc[nf][0] *= c0; oacc[nf][1] *= c0;
            oacc[nf][2] *= c1; oacc[nf][3] *= c1;
        }

        __syncthreads();   // all warps done reading Ks — safe to overwrite with P

        // Store P (tf32 bits) into the warp's private 16 rows of Ks
        {
            unsigned* p0 = Ks + (w * 16 + g) * KSTRIDE;
            unsigned* p1 = Ks + (w * 16 + g + 8) * KSTRIDE;
#pragma unroll
            for (int nf = 0; nf < 8; nf++) {
                p0[nf * 8 + 2 * l4]     = f2tf(sacc[nf][0]);
                p0[nf * 8 + 2 * l4 + 1] = f2tf(sacc[nf][1]);
                p1[nf * 8 + 2 * l4]     = f2tf(sacc[nf][2]);
                p1[nf * 8 + 2 * l4 + 1] = f2tf(sacc[nf][3]);
            }
        }
        __syncwarp();      // warp-local store->load visibility

        // O += P @ V
#pragma unroll
        for (int ks = 0; ks < 8; ks++) {
            unsigned pa[4];
            const unsigned* p0 = Ks + (w * 16 + g) * KSTRIDE;
            const unsigned* p1 = Ks + (w * 16 + g + 8) * KSTRIDE;
            pa[0] = p0[ks * 8 + l4];
            pa[1] = p1[ks * 8 + l4];
            pa[2] = p0[ks * 8 + l4 + 4];
            pa[3] = p1[ks * 8 + l4 + 4];
            const unsigned* v0 = Vs + (ks * 8 + l4) * VSTRIDE;
            const unsigned* v1 = Vs + (ks * 8 + l4 + 4) * VSTRIDE;
#pragma unroll
            for (int nf = 0; nf < 8; nf++) {
                unsigned b[2];
                b[0] = v0[nf * 8 + g];
                b[1] = v1[nf * 8 + g];
                mma_tf32(oacc[nf], pa, b);
            }
        }
    }

    // Epilogue: normalize, write [B,N,H*D]
    float il0 = 1.0f / l0, il1 = 1.0f / l1;
    size_t base0 = ((size_t)bb * SEQ + (qbase + g)) * EMB + h * HDIM;
    size_t base1 = base0 + (size_t)8 * EMB;
#pragma unroll
    for (int nf = 0; nf < 8; nf++) {
        int col = nf * 8 + 2 * l4;
        g_attn[base0 + col]     = oacc[nf][0] * il0;
        g_attn[base0 + col + 1] = oacc[nf][1] * il0;
        g_attn[base1 + col]     = oacc[nf][2] * il1;
        g_attn[base1 + col + 1] = oacc[nf][3] * il1;
    }
}

// ---------------------------------------------------------------------------
// Launch
// ---------------------------------------------------------------------------
extern "C" void kernel_launch(void* const* d_in, const int* in_sizes, int n_in,
                              void* d_out, int out_size)
{
    const float* x     = (const float*)d_in[0];
    const float* qkv_w = (const float*)d_in[1];
    const float* qkv_b = (const float*)d_in[2];
    const float* out_w = (const float*)d_in[3];
    const float* out_b = (const float*)d_in[4];
    float* out = (float*)d_out;

    dim3 g1(ROWS / 128, QKVN / 128);     // 64 x 24
    qkv_gemm_kernel<<<g1, 256>>>(x, qkv_w, qkv_b);

    dim3 g2(SEQ / 64, HEADS, BATCH);     // 32 x 16 x 4
    attn_kernel<<<g2, 128>>>();

    dim3 g3(ROWS / 128, EMB / 128);      // 64 x 8
    proj_gemm_kernel<<<g3, 256>>>(out_w, out_b, out);
}

// round 5
// speedup vs baseline: 3.2910x; 1.0586x over previous
#include <cuda_runtime.h>
#include <cuda_bf16.h>
#include <math.h>

// Problem constants
#define BATCH 4
#define SEQ   2048
#define EMB   1024
#define HEADS 16
#define HDIM  64
#define QKVN  (3 * EMB)          // 3072
#define ROWS  (BATCH * SEQ)      // 8192

// ---------------------------------------------------------------------------
// Scratch — head-major Q/K/V + attention output
// ---------------------------------------------------------------------------
__device__ float g_q[BATCH * HEADS * SEQ * HDIM];
__device__ float g_k[BATCH * HEADS * SEQ * HDIM];
__device__ float g_v[BATCH * HEADS * SEQ * HDIM];
__device__ float g_attn[ROWS * EMB];   // [B,N,H*D]

// ---------------------------------------------------------------------------
// Helpers: tf32 convert, tf32 MMA, cp.async
// ---------------------------------------------------------------------------
__device__ __forceinline__ unsigned f2tf(float f) {
    unsigned u;
    asm("cvt.rna.tf32.f32 %0, %1;" : "=r"(u) : "f"(f));
    return u;
}

__device__ __forceinline__ void mma_tf32(float d[4], const unsigned a[4],
                                         const unsigned b[2]) {
    asm volatile(
        "mma.sync.aligned.m16n8k8.row.col.f32.tf32.tf32.f32 "
        "{%0,%1,%2,%3}, {%4,%5,%6,%7}, {%8,%9}, {%0,%1,%2,%3};"
        : "+f"(d[0]), "+f"(d[1]), "+f"(d[2]), "+f"(d[3])
        : "r"(a[0]), "r"(a[1]), "r"(a[2]), "r"(a[3]),
          "r"(b[0]), "r"(b[1]));
}

__device__ __forceinline__ void cp16(void* smem_dst, const void* gmem_src) {
    unsigned s = (unsigned)__cvta_generic_to_shared(smem_dst);
    asm volatile("cp.async.cg.shared.global [%0], [%1], 16;"
                 :: "r"(s), "l"(gmem_src));
}
#define CP_COMMIT() asm volatile("cp.async.commit_group;" ::: "memory")
#define CP_WAIT1()  asm volatile("cp.async.wait_group 1;"  ::: "memory")

// ---------------------------------------------------------------------------
// GEMM mainloop: C[128x128] = A[m0..,1024] x B[j0..,1024]^T, both row-major
// K-contiguous. 128 threads = 4 warps (2x2), warp tile 64x64.
// Double-buffered cp.async staging of raw fp32; tf32 convert at fragment load.
// acc[mi][nf][slot]: rows wm*64+mi*16+{g,g+8}, cols wn*64+nf*8+2*l4+{0,1}
// ---------------------------------------------------------------------------
#define SPAD 20           // fp32 row stride in smem (conflict-free frag reads)
#define STAGE (128 * SPAD)

__device__ __forceinline__ void gemm_mainloop(
    const float* __restrict__ Ag, const float* __restrict__ Bg,
    int m0, int j0, float* As, float* Bs, float acc[4][8][4])
{
    const int tid  = threadIdx.x;
    const int lane = tid & 31;
    const int w    = tid >> 5;
    const int g    = lane >> 2;
    const int l4   = lane & 3;
    const int wm   = w >> 1;
    const int wn   = w & 1;

#pragma unroll
    for (int mi = 0; mi < 4; mi++)
#pragma unroll
        for (int nf = 0; nf < 8; nf++)
#pragma unroll
            for (int s = 0; s < 4; s++) acc[mi][nf][s] = 0.0f;

    auto stage = [&](int slab, int buf) {
        const int k0 = slab * 16;
        float* Ad = As + buf * STAGE;
        float* Bd = Bs + buf * STAGE;
#pragma unroll
        for (int it = 0; it < 4; it++) {
            int e   = it * 128 + tid;
            int row = e >> 2;
            int c4  = (e & 3) * 4;
            cp16(Ad + row * SPAD + c4, Ag + (size_t)(m0 + row) * EMB + k0 + c4);
            cp16(Bd + row * SPAD + c4, Bg + (size_t)(j0 + row) * EMB + k0 + c4);
        }
    };

    stage(0, 0); CP_COMMIT();
    stage(1, 1); CP_COMMIT();

    for (int s = 0; s < 64; s++) {
        CP_WAIT1();
        __syncthreads();
        const float* Ab = As + (s & 1) * STAGE;
        const float* Bb = Bs + (s & 1) * STAGE;

#pragma unroll
        for (int ks = 0; ks < 2; ks++) {
            const int kk = ks * 8;
            unsigned a[4][4];
#pragma unroll
            for (int mi = 0; mi < 4; mi++) {
                int mr = wm * 64 + mi * 16 + g;
                a[mi][0] = f2tf(Ab[mr * SPAD + kk + l4]);
                a[mi][1] = f2tf(Ab[(mr + 8) * SPAD + kk + l4]);
                a[mi][2] = f2tf(Ab[mr * SPAD + kk + l4 + 4]);
                a[mi][3] = f2tf(Ab[(mr + 8) * SPAD + kk + l4 + 4]);
            }
#pragma unroll
            for (int nf = 0; nf < 8; nf++) {
                int nr = wn * 64 + nf * 8 + g;
                unsigned b[2];
                b[0] = f2tf(Bb[nr * SPAD + kk + l4]);
                b[1] = f2tf(Bb[nr * SPAD + kk + l4 + 4]);
#pragma unroll
                for (int mi = 0; mi < 4; mi++)
                    mma_tf32(acc[mi][nf], a[mi], b);
            }
        }
        __syncthreads();
        if (s + 2 < 64) stage(s + 2, s & 1);
        CP_COMMIT();
    }
}

// ---------------------------------------------------------------------------
// Kernel 1: QKV GEMM + scatter into head-major g_q/g_k/g_v
// ---------------------------------------------------------------------------
__global__ __launch_bounds__(128) void qkv_gemm_kernel(
    const float* __restrict__ x,
    const float* __restrict__ w,
    const float* __restrict__ bias)
{
    __shared__ __align__(16) float As[2 * STAGE];
    __shared__ __align__(16) float Bs[2 * STAGE];
    float acc[4][8][4];
    const int m0 = blockIdx.x * 128;
    const int j0 = blockIdx.y * 128;
    gemm_mainloop(x, w, m0, j0, As, Bs, acc);

    const int lane = threadIdx.x & 31;
    const int wrp  = threadIdx.x >> 5;
    const int g = lane >> 2, l4 = lane & 3;
    const int wm = wrp >> 1, wn = wrp & 1;

#pragma unroll
    for (int mi = 0; mi < 4; mi++)
#pragma unroll
        for (int rr = 0; rr < 2; rr++) {
            int m = m0 + wm * 64 + mi * 16 + g + rr * 8;
            int b = m >> 11;
            int n = m & (SEQ - 1);
#pragma unroll
            for (int nf = 0; nf < 8; nf++)
#pragma unroll
                for (int cc = 0; cc < 2; cc++) {
                    int jj = j0 + wn * 64 + nf * 8 + 2 * l4 + cc;
                    float v = acc[mi][nf][rr * 2 + cc] + bias[jj];
                    int which = jj >> 10;
                    int rem = jj & 1023;
                    int h = rem >> 6, d = rem & 63;
                    float* dst = (which == 0) ? g_q : (which == 1) ? g_k : g_v;
                    dst[((((size_t)b * HEADS + h) * SEQ) + n) * HDIM + d] = v;
                }
        }
}

// ---------------------------------------------------------------------------
// Kernel 3: out-proj GEMM
// ---------------------------------------------------------------------------
__global__ __launch_bounds__(128) void proj_gemm_kernel(
    const float* __restrict__ w,
    const float* __restrict__ bias,
    float* __restrict__ out)
{
    __shared__ __align__(16) float As[2 * STAGE];
    __shared__ __align__(16) float Bs[2 * STAGE];
    float acc[4][8][4];
    const int m0 = blockIdx.x * 128;
    const int j0 = blockIdx.y * 128;
    gemm_mainloop(g_attn, w, m0, j0, As, Bs, acc);

    const int lane = threadIdx.x & 31;
    const int wrp  = threadIdx.x >> 5;
    const int g = lane >> 2, l4 = lane & 3;
    const int wm = wrp >> 1, wn = wrp & 1;

#pragma unroll
    for (int mi = 0; mi < 4; mi++)
#pragma unroll
        for (int rr = 0; rr < 2; rr++) {
            size_t m = m0 + wm * 64 + mi * 16 + g + rr * 8;
#pragma unroll
            for (int nf = 0; nf < 8; nf++)
#pragma unroll
                for (int cc = 0; cc < 2; cc++) {
                    int jj = j0 + wn * 64 + nf * 8 + 2 * l4 + cc;
                    out[m * EMB + jj] = acc[mi][nf][rr * 2 + cc] + bias[jj];
                }
        }
}

// ---------------------------------------------------------------------------
// Kernel 2: flash attention, tf32 tensor cores, cp.async double-buffered K/V.
// 128 threads (4 warps), 64-query tile; warp w owns q rows w*16..+16.
// Q persistent in A-fragments, scale 0.125*log2e folded in (exp2 softmax).
// Key tiles of 32, fp32 in smem (Kf stride 68, Vf stride 72), tf32 at load.
// P goes through a warp-private smem buffer (stride 36) — only __syncwarp.
// ---------------------------------------------------------------------------
#define KT2     32
#define KFS     68
#define VFS     72
#define PSTRIDE 36

__global__ __launch_bounds__(128) void attn_kernel()
{
    __shared__ __align__(16) float Kf[2 * KT2 * KFS];   // 17.4 KB
    __shared__ __align__(16) float Vf[2 * KT2 * VFS];   // 18.4 KB
    __shared__ unsigned Pm[4][16 * PSTRIDE];            //  9.2 KB

    const int tid  = threadIdx.x;
    const int lane = tid & 31;
    const int w    = tid >> 5;
    const int g    = lane >> 2;
    const int l4   = lane & 3;
    const int q0   = blockIdx.x * 64;
    const int h    = blockIdx.y;
    const int bb   = blockIdx.z;

    const size_t head_off = (((size_t)bb * HEADS + h) * SEQ) * HDIM;
    const float* qg = g_q + head_off;
    const float* kg = g_k + head_off;
    const float* vg = g_v + head_off;

    // Persistent Q fragments; fold 1/sqrt(64) * log2(e) for exp2-domain softmax
    const float QSCALE = 0.125f * 1.4426950408889634f;
    const int qbase = q0 + w * 16;
    unsigned qa[8][4];
    {
        const float* qr0 = qg + (size_t)(qbase + g) * HDIM;
        const float* qr1 = qg + (size_t)(qbase + g + 8) * HDIM;
#pragma unroll
        for (int kf = 0; kf < 8; kf++) {
            qa[kf][0] = f2tf(qr0[kf * 8 + l4] * QSCALE);
            qa[kf][1] = f2tf(qr1[kf * 8 + l4] * QSCALE);
            qa[kf][2] = f2tf(qr0[kf * 8 + l4 + 4] * QSCALE);
            qa[kf][3] = f2tf(qr1[kf * 8 + l4 + 4] * QSCALE);
        }
    }

    auto stage2 = [&](int t, int buf) {
        const int kt = t * KT2;
        float* Kd = Kf + buf * KT2 * KFS;
        float* Vd = Vf + buf * KT2 * VFS;
        // K tile: 32 rows x 64 cols = 512 float4; 128 threads x 4
#pragma unroll
        for (int it = 0; it < 4; it++) {
            int e   = it * 128 + tid;
            int row = e >> 4;
            int c4  = (e & 15) * 4;
            cp16(Kd + row * KFS + c4, kg + (size_t)(kt + row) * HDIM + c4);
        }
#pragma unroll
        for (int it = 0; it < 4; it++) {
            int e   = it * 128 + tid;
            int row = e >> 4;
            int c4  = (e & 15) * 4;
            cp16(Vd + row * VFS + c4, vg + (size_t)(kt + row) * HDIM + c4);
        }
    };

    float oacc[8][4];
#pragma unroll
    for (int nf = 0; nf < 8; nf++)
#pragma unroll
        for (int s = 0; s < 4; s++) oacc[nf][s] = 0.0f;
    float mx0 = -1e30f, mx1 = -1e30f, l0 = 0.0f, l1 = 0.0f;

    stage2(0, 0); CP_COMMIT();
    stage2(1, 1); CP_COMMIT();

    const int NT = SEQ / KT2;    // 64 tiles
    for (int t = 0; t < NT; t++) {
        CP_WAIT1();
        __syncthreads();
        const float* Kb = Kf + (t & 1) * KT2 * KFS;
        const float* Vb = Vf + (t & 1) * KT2 * VFS;

        // S = Qs @ K^T : warp computes 16 x 32
        float sacc[4][4];
#pragma unroll
        for (int nf = 0; nf < 4; nf++)
#pragma unroll
            for (int s = 0; s < 4; s++) sacc[nf][s] = 0.0f;

#pragma unroll
        for (int nf = 0; nf < 4; nf++) {
            const float* kr = Kb + (nf * 8 + g) * KFS;
#pragma unroll
            for (int kf = 0; kf < 8; kf++) {
                unsigned b[2];
                b[0] = f2tf(kr[kf * 8 + l4]);
                b[1] = f2tf(kr[kf * 8 + l4 + 4]);
                mma_tf32(sacc[nf], qa[kf], b);
            }
        }

        // Online softmax (exp2 domain), rows g and g+8
        float tm0 = -1e30f, tm1 = -1e30f;
#pragma unroll
        for (int nf = 0; nf < 4; nf++) {
            tm0 = fmaxf(tm0, fmaxf(sacc[nf][0], sacc[nf][1]));
            tm1 = fmaxf(tm1, fmaxf(sacc[nf][2], sacc[nf][3]));
        }
        tm0 = fmaxf(tm0, __shfl_xor_sync(0xffffffffu, tm0, 1));
        tm0 = fmaxf(tm0, __shfl_xor_sync(0xffffffffu, tm0, 2));
        tm1 = fmaxf(tm1, __shfl_xor_sync(0xffffffffu, tm1, 1));
        tm1 = fmaxf(tm1, __shfl_xor_sync(0xffffffffu, tm1, 2));

        float nm0 = fmaxf(mx0, tm0), nm1 = fmaxf(mx1, tm1);
        float c0 = exp2f(mx0 - nm0), c1 = exp2f(mx1 - nm1);
        mx0 = nm0; mx1 = nm1;

        float rs0 = 0.0f, rs1 = 0.0f;
#pragma unroll
        for (int nf = 0; nf < 4; nf++) {
            sacc[nf][0] = exp2f(sacc[nf][0] - nm0); rs0 += sacc[nf][0];
            sacc[nf][1] = exp2f(sacc[nf][1] - nm0); rs0 += sacc[nf][1];
            sacc[nf][2] = exp2f(sacc[nf][2] - nm1); rs1 += sacc[nf][2];
            sacc[nf][3] = exp2f(sacc[nf][3] - nm1); rs1 += sacc[nf][3];
        }
        rs0 += __shfl_xor_sync(0xffffffffu, rs0, 1);
        rs0 += __shfl_xor_sync(0xffffffffu, rs0, 2);
        rs1 += __shfl_xor_sync(0xffffffffu, rs1, 1);
        rs1 += __shfl_xor_sync(0xffffffffu, rs1, 2);
        l0 = l0 * c0 + rs0;
        l1 = l1 * c1 + rs1;
#pragma unroll
        for (int nf = 0; nf < 8; nf++) {
            oacc[nf][0] *= c0; oacc[nf][1] *= c0;
            oacc[nf][2] *= c1; oacc[nf][3] *= c1;
        }

        // P (tf32) into warp-private buffer — no cross-warp sync needed
        {
            unsigned* p0 = Pm[w] + g * PSTRIDE;
            unsigned* p1 = Pm[w] + (g + 8) * PSTRIDE;
#pragma unroll
            for (int nf = 0; nf < 4; nf++) {
                p0[nf * 8 + 2 * l4]     = f2tf(sacc[nf][0]);
                p0[nf * 8 + 2 * l4 + 1] = f2tf(sacc[nf][1]);
                p1[nf * 8 + 2 * l4]     = f2tf(sacc[nf][2]);
                p1[nf * 8 + 2 * l4 + 1] = f2tf(sacc[nf][3]);
            }
        }
        __syncwarp();

        // O += P @ V
#pragma unroll
        for (int ks = 0; ks < 4; ks++) {
            unsigned pa[4];
            const unsigned* p0 = Pm[w] + g * PSTRIDE;
            const unsigned* p1 = Pm[w] + (g + 8) * PSTRIDE;
            pa[0] = p0[ks * 8 + l4];
            pa[1] = p1[ks * 8 + l4];
            pa[2] = p0[ks * 8 + l4 + 4];
            pa[3] = p1[ks * 8 + l4 + 4];
            const float* v0 = Vb + (ks * 8 + l4) * VFS;
            const float* v1 = Vb + (ks * 8 + l4 + 4) * VFS;
#pragma unroll
            for (int nf = 0; nf < 8; nf++) {
                unsigned b[2];
                b[0] = f2tf(v0[nf * 8 + g]);
                b[1] = f2tf(v1[nf * 8 + g]);
                mma_tf32(oacc[nf], pa, b);
            }
        }

        __syncthreads();
        if (t + 2 < NT) stage2(t + 2, t & 1);
        CP_COMMIT();
    }

    // Epilogue: normalize, write [B,N,H*D]
    float il0 = 1.0f / l0, il1 = 1.0f / l1;
    size_t base0 = ((size_t)bb * SEQ + (qbase + g)) * EMB + h * HDIM;
    size_t base1 = base0 + (size_t)8 * EMB;
#pragma unroll
    for (int nf = 0; nf < 8; nf++) {
        int col = nf * 8 + 2 * l4;
        g_attn[base0 + col]     = oacc[nf][0] * il0;
        g_attn[base0 + col + 1] = oacc[nf][1] * il0;
        g_attn[base1 + col]     = oacc[nf][2] * il1;
        g_attn[base1 + col + 1] = oacc[nf][3] * il1;
    }
}

// ---------------------------------------------------------------------------
// Launch
// ---------------------------------------------------------------------------
extern "C" void kernel_launch(void* const* d_in, const int* in_sizes, int n_in,
                              void* d_out, int out_size)
{
    const float* x     = (const float*)d_in[0];
    const float* qkv_w = (const float*)d_in[1];
    const float* qkv_b = (const float*)d_in[2];
    const float* out_w = (const float*)d_in[3];
    const float* out_b = (const float*)d_in[4];
    float* out = (float*)d_out;

    dim3 g1(ROWS / 128, QKVN / 128);     // 64 x 24
    qkv_gemm_kernel<<<g1, 128>>>(x, qkv_w, qkv_b);

    dim3 g2(SEQ / 64, HEADS, BATCH);     // 32 x 16 x 4
    attn_kernel<<<g2, 128>>>();

    dim3 g3(ROWS / 128, EMB / 128);      // 64 x 8
    proj_gemm_kernel<<<g3, 128>>>(out_w, out_b, out);
}

// round 7
// speedup vs baseline: 3.6210x; 1.1003x over previous
#include <cuda_runtime.h>
#include <cuda_bf16.h>
#include <math.h>

// Problem constants
#define BATCH 4
#define SEQ   2048
#define EMB   1024
#define HEADS 16
#define HDIM  64
#define QKVN  (3 * EMB)          // 3072
#define ROWS  (BATCH * SEQ)      // 8192

// ---------------------------------------------------------------------------
// Scratch — pre-rounded inputs, head-major Q/K/V, attention output.
// All values stored here are RN-rounded to tf32 (low 13 mantissa bits zero),
// so raw-bit tf32 MMA operands built from them have exact RN semantics.
// ---------------------------------------------------------------------------
__device__ float g_x   [ROWS * EMB];        // tf32(x)
__device__ float g_wqkv[QKVN * EMB];        // tf32(qkv_w)
__device__ float g_wout[EMB * EMB];         // tf32(out_w)
__device__ float g_q[BATCH * HEADS * SEQ * HDIM];
__device__ float g_k[BATCH * HEADS * SEQ * HDIM];
__device__ float g_v[BATCH * HEADS * SEQ * HDIM];
__device__ float g_attn[ROWS * EMB];        // [B,N,H*D], tf32-rounded

// ---------------------------------------------------------------------------
// Helpers
// ---------------------------------------------------------------------------
__device__ __forceinline__ unsigned f2tf(float f) {   // RN round to tf32
    unsigned u;
    asm("cvt.rna.tf32.f32 %0, %1;" : "=r"(u) : "f"(f));
    return u;
}
__device__ __forceinline__ float f2tff(float f) { return __uint_as_float(f2tf(f)); }

__device__ __forceinline__ float fex2(float x) {      // fast exp2
    float r;
    asm("ex2.approx.f32 %0, %1;" : "=f"(r) : "f"(x));
    return r;
}

__device__ __forceinline__ void mma_tf32(float d[4], const unsigned a[4],
                                         const unsigned b[2]) {
    asm volatile(
        "mma.sync.aligned.m16n8k8.row.col.f32.tf32.tf32.f32 "
        "{%0,%1,%2,%3}, {%4,%5,%6,%7}, {%8,%9}, {%0,%1,%2,%3};"
        : "+f"(d[0]), "+f"(d[1]), "+f"(d[2]), "+f"(d[3])
        : "r"(a[0]), "r"(a[1]), "r"(a[2]), "r"(a[3]),
          "r"(b[0]), "r"(b[1]));
}

__device__ __forceinline__ void cp16(void* smem_dst, const void* gmem_src) {
    unsigned s = (unsigned)__cvta_generic_to_shared(smem_dst);
    asm volatile("cp.async.cg.shared.global [%0], [%1], 16;"
                 :: "r"(s), "l"(gmem_src));
}
#define CP_COMMIT() asm volatile("cp.async.commit_group;" ::: "memory")
#define CP_WAIT1()  asm volatile("cp.async.wait_group 1;"  ::: "memory")

// ---------------------------------------------------------------------------
// Pre-kernel: RN-round a whole buffer to tf32 (vectorized, grid-stride)
// ---------------------------------------------------------------------------
__global__ __launch_bounds__(256) void cvt_tf32_kernel(
    const float4* __restrict__ src, float4* __restrict__ dst, int n4)
{
    int i = blockIdx.x * blockDim.x + threadIdx.x;
    int stride = gridDim.x * blockDim.x;
    for (; i < n4; i += stride) {
        float4 v = src[i];
        v.x = f2tff(v.x); v.y = f2tff(v.y);
        v.z = f2tff(v.z); v.w = f2tff(v.w);
        dst[i] = v;
    }
}

// ---------------------------------------------------------------------------
// GEMM mainloop: C[128x128] = A[m0..,1024] x B[j0..,1024]^T, both row-major
// K-contiguous, inputs pre-rounded to tf32. 128 threads = 4 warps (2x2),
// warp tile 64x64. Double-buffered cp.async; raw-bit fragments (== RN tf32).
// acc[mi][nf][slot]: rows wm*64+mi*16+{g,g+8}, cols wn*64+nf*8+2*l4+{0,1}
// ---------------------------------------------------------------------------
#define SPAD 20
#define STAGE (128 * SPAD)

__device__ __forceinline__ void gemm_mainloop(
    const float* __restrict__ Ag, const float* __restrict__ Bg,
    int m0, int j0, float* As, float* Bs, float acc[4][8][4])
{
    const int tid  = threadIdx.x;
    const int lane = tid & 31;
    const int w    = tid >> 5;
    const int g    = lane >> 2;
    const int l4   = lane & 3;
    const int wm   = w >> 1;
    const int wn   = w & 1;

#pragma unroll
    for (int mi = 0; mi < 4; mi++)
#pragma unroll
        for (int nf = 0; nf < 8; nf++)
#pragma unroll
            for (int s = 0; s < 4; s++) acc[mi][nf][s] = 0.0f;

    auto stage = [&](int slab, int buf) {
        const int k0 = slab * 16;
        float* Ad = As + buf * STAGE;
        float* Bd = Bs + buf * STAGE;
#pragma unroll
        for (int it = 0; it < 4; it++) {
            int e   = it * 128 + tid;
            int row = e >> 2;
            int c4  = (e & 3) * 4;
            cp16(Ad + row * SPAD + c4, Ag + (size_t)(m0 + row) * EMB + k0 + c4);
            cp16(Bd + row * SPAD + c4, Bg + (size_t)(j0 + row) * EMB + k0 + c4);
        }
    };

    stage(0, 0); CP_COMMIT();
    stage(1, 1); CP_COMMIT();

    for (int s = 0; s < 64; s++) {
        CP_WAIT1();
        __syncthreads();
        const float* Ab = As + (s & 1) * STAGE;
        const float* Bb = Bs + (s & 1) * STAGE;

#pragma unroll
        for (int ks = 0; ks < 2; ks++) {
            const int kk = ks * 8;
            unsigned a[4][4];
#pragma unroll
            for (int mi = 0; mi < 4; mi++) {
                int mr = wm * 64 + mi * 16 + g;
                a[mi][0] = __float_as_uint(Ab[mr * SPAD + kk + l4]);
                a[mi][1] = __float_as_uint(Ab[(mr + 8) * SPAD + kk + l4]);
                a[mi][2] = __float_as_uint(Ab[mr * SPAD + kk + l4 + 4]);
                a[mi][3] = __float_as_uint(Ab[(mr + 8) * SPAD + kk + l4 + 4]);
            }
#pragma unroll
            for (int nf = 0; nf < 8; nf++) {
                int nr = wn * 64 + nf * 8 + g;
                unsigned b[2];
                b[0] = __float_as_uint(Bb[nr * SPAD + kk + l4]);
                b[1] = __float_as_uint(Bb[nr * SPAD + kk + l4 + 4]);
#pragma unroll
                for (int mi = 0; mi < 4; mi++)
                    mma_tf32(acc[mi][nf], a[mi], b);
            }
        }
        __syncthreads();
        if (s + 2 < 64) stage(s + 2, s & 1);
        CP_COMMIT();
    }
}

// ---------------------------------------------------------------------------
// Kernel 1: QKV GEMM + scatter into head-major g_q/g_k/g_v.
// Outputs RN-rounded to tf32 so downstream raw-bit MMA reads are RN-exact.
// ---------------------------------------------------------------------------
__global__ __launch_bounds__(128) void qkv_gemm_kernel(
    const float* __restrict__ bias)
{
    __shared__ __align__(16) float As[2 * STAGE];
    __shared__ __align__(16) float Bs[2 * STAGE];
    float acc[4][8][4];
    const int m0 = blockIdx.x * 128;
    const int j0 = blockIdx.y * 128;
    gemm_mainloop(g_x, g_wqkv, m0, j0, As, Bs, acc);

    const int lane = threadIdx.x & 31;
    const int wrp  = threadIdx.x >> 5;
    const int g = lane >> 2, l4 = lane & 3;
    const int wm = wrp >> 1, wn = wrp & 1;

#pragma unroll
    for (int mi = 0; mi < 4; mi++)
#pragma unroll
        for (int rr = 0; rr < 2; rr++) {
            int m = m0 + wm * 64 + mi * 16 + g + rr * 8;
            int b = m >> 11;
            int n = m & (SEQ - 1);
#pragma unroll
            for (int nf = 0; nf < 8; nf++)
#pragma unroll
                for (int cc = 0; cc < 2; cc++) {
                    int jj = j0 + wn * 64 + nf * 8 + 2 * l4 + cc;
                    float v = f2tff(acc[mi][nf][rr * 2 + cc] + bias[jj]);
                    int which = jj >> 10;
                    int rem = jj & 1023;
                    int h = rem >> 6, d = rem & 63;
                    float* dst = (which == 0) ? g_q : (which == 1) ? g_k : g_v;
                    dst[((((size_t)b * HEADS + h) * SEQ) + n) * HDIM + d] = v;
                }
        }
}

// ---------------------------------------------------------------------------
// Kernel 3: out-proj GEMM (final output stays full fp32)
// ---------------------------------------------------------------------------
__global__ __launch_bounds__(128) void proj_gemm_kernel(
    const float* __restrict__ bias,
    float* __restrict__ out)
{
    __shared__ __align__(16) float As[2 * STAGE];
    __shared__ __align__(16) float Bs[2 * STAGE];
    float acc[4][8][4];
    const int m0 = blockIdx.x * 128;
    const int j0 = blockIdx.y * 128;
    gemm_mainloop(g_attn, g_wout, m0, j0, As, Bs, acc);

    const int lane = threadIdx.x & 31;
    const int wrp  = threadIdx.x >> 5;
    const int g = lane >> 2, l4 = lane & 3;
    const int wm = wrp >> 1, wn = wrp & 1;

#pragma unroll
    for (int mi = 0; mi < 4; mi++)
#pragma unroll
        for (int rr = 0; rr < 2; rr++) {
            size_t m = m0 + wm * 64 + mi * 16 + g + rr * 8;
#pragma unroll
            for (int nf = 0; nf < 8; nf++)
#pragma unroll
                for (int cc = 0; cc < 2; cc++) {
                    int jj = j0 + wn * 64 + nf * 8 + 2 * l4 + cc;
                    out[m * EMB + jj] = acc[mi][nf][rr * 2 + cc] + bias[jj];
                }
        }
}

// ---------------------------------------------------------------------------
// Kernel 2: flash attention, tf32 tensor cores, cp.async double-buffered K/V.
// 128 threads (4 warps), 64-query tile; warp w owns q rows w*16..+16.
// Q persistent in A-fragments (RN cvt, scale 0.125*log2e folded for exp2).
// K/V pre-rounded -> raw-bit fragments are RN-exact. P RN-rounded at store.
// ---------------------------------------------------------------------------
#define KT2     32
#define KFS     68
#define VFS     72
#define PSTRIDE 36

__global__ __launch_bounds__(128) void attn_kernel()
{
    __shared__ __align__(16) float Kf[2 * KT2 * KFS];
    __shared__ __align__(16) float Vf[2 * KT2 * VFS];
    __shared__ unsigned Pm[4][16 * PSTRIDE];

    const int tid  = threadIdx.x;
    const int lane = tid & 31;
    const int w    = tid >> 5;
    const int g    = lane >> 2;
    const int l4   = lane & 3;
    const int q0   = blockIdx.x * 64;
    const int h    = blockIdx.y;
    const int bb   = blockIdx.z;

    const size_t head_off = (((size_t)bb * HEADS + h) * SEQ) * HDIM;
    const float* qg = g_q + head_off;
    const float* kg = g_k + head_off;
    const float* vg = g_v + head_off;

    const float QSCALE = 0.125f * 1.4426950408889634f;
    const int qbase = q0 + w * 16;
    unsigned qa[8][4];
    {
        const float* qr0 = qg + (size_t)(qbase + g) * HDIM;
        const float* qr1 = qg + (size_t)(qbase + g + 8) * HDIM;
#pragma unroll
        for (int kf = 0; kf < 8; kf++) {
            qa[kf][0] = f2tf(qr0[kf * 8 + l4] * QSCALE);
            qa[kf][1] = f2tf(qr1[kf * 8 + l4] * QSCALE);
            qa[kf][2] = f2tf(qr0[kf * 8 + l4 + 4] * QSCALE);
            qa[kf][3] = f2tf(qr1[kf * 8 + l4 + 4] * QSCALE);
        }
    }

    auto stage2 = [&](int t, int buf) {
        const int kt = t * KT2;
        float* Kd = Kf + buf * KT2 * KFS;
        float* Vd = Vf + buf * KT2 * VFS;
#pragma unroll
        for (int it = 0; it < 4; it++) {
            int e   = it * 128 + tid;
            int row = e >> 4;
            int c4  = (e & 15) * 4;
            cp16(Kd + row * KFS + c4, kg + (size_t)(kt + row) * HDIM + c4);
        }
#pragma unroll
        for (int it = 0; it < 4; it++) {
            int e   = it * 128 + tid;
            int row = e >> 4;
            int c4  = (e & 15) * 4;
            cp16(Vd + row * VFS + c4, vg + (size_t)(kt + row) * HDIM + c4);
        }
    };

    float oacc[8][4];
#pragma unroll
    for (int nf = 0; nf < 8; nf++)
#pragma unroll
        for (int s = 0; s < 4; s++) oacc[nf][s] = 0.0f;
    float mx0 = -1e30f, mx1 = -1e30f, l0 = 0.0f, l1 = 0.0f;

    stage2(0, 0); CP_COMMIT();
    stage2(1, 1); CP_COMMIT();

    const int NT = SEQ / KT2;    // 64 tiles
    for (int t = 0; t < NT; t++) {
        CP_WAIT1();
        __syncthreads();
        const float* Kb = Kf + (t & 1) * KT2 * KFS;
        const float* Vb = Vf + (t & 1) * KT2 * VFS;

        // S = Qs @ K^T : warp computes 16 x 32
        float sacc[4][4];
#pragma unroll
        for (int nf = 0; nf < 4; nf++)
#pragma unroll
            for (int s = 0; s < 4; s++) sacc[nf][s] = 0.0f;

#pragma unroll
        for (int nf = 0; nf < 4; nf++) {
            const float* kr = Kb + (nf * 8 + g) * KFS;
#pragma unroll
            for (int kf = 0; kf < 8; kf++) {
                unsigned b[2];
                b[0] = __float_as_uint(kr[kf * 8 + l4]);
                b[1] = __float_as_uint(kr[kf * 8 + l4 + 4]);
                mma_tf32(sacc[nf], qa[kf], b);
            }
        }

        // Online softmax (exp2 domain)
        float tm0 = -1e30f, tm1 = -1e30f;
#pragma unroll
        for (int nf = 0; nf < 4; nf++) {
            tm0 = fmaxf(tm0, fmaxf(sacc[nf][0], sacc[nf][1]));
            tm1 = fmaxf(tm1, fmaxf(sacc[nf][2], sacc[nf][3]));
        }
        tm0 = fmaxf(tm0, __shfl_xor_sync(0xffffffffu, tm0, 1));
        tm0 = fmaxf(tm0, __shfl_xor_sync(0xffffffffu, tm0, 2));
        tm1 = fmaxf(tm1, __shfl_xor_sync(0xffffffffu, tm1, 1));
        tm1 = fmaxf(tm1, __shfl_xor_sync(0xffffffffu, tm1, 2));

        float nm0 = fmaxf(mx0, tm0), nm1 = fmaxf(mx1, tm1);
        float c0 = fex2(mx0 - nm0), c1 = fex2(mx1 - nm1);
        mx0 = nm0; mx1 = nm1;

        float rs0 = 0.0f, rs1 = 0.0f;
#pragma unroll
        for (int nf = 0; nf < 4; nf++) {
            sacc[nf][0] = fex2(sacc[nf][0] - nm0); rs0 += sacc[nf][0];
            sacc[nf][1] = fex2(sacc[nf][1] - nm0); rs0 += sacc[nf][1];
            sacc[nf][2] = fex2(sacc[nf][2] - nm1); rs1 += sacc[nf][2];
            sacc[nf][3] = fex2(sacc[nf][3] - nm1); rs1 += sacc[nf][3];
        }
        rs0 += __shfl_xor_sync(0xffffffffu, rs0, 1);
        rs0 += __shfl_xor_sync(0xffffffffu, rs0, 2);
        rs1 += __shfl_xor_sync(0xffffffffu, rs1, 1);
        rs1 += __shfl_xor_sync(0xffffffffu, rs1, 2);
        l0 = l0 * c0 + rs0;
        l1 = l1 * c1 + rs1;
#pragma unroll
        for (int nf = 0; nf < 8; nf++) {
            oacc[nf][0] *= c0; oacc[nf][1] *= c0;
            oacc[nf][2] *= c1; oacc[nf][3] *= c1;
        }

        // P RN-rounded into warp-private buffer (only __syncwarp needed)
        {
            unsigned* p0 = Pm[w] + g * PSTRIDE;
            unsigned* p1 = Pm[w] + (g + 8) * PSTRIDE;
#pragma unroll
            for (int nf = 0; nf < 4; nf++) {
                p0[nf * 8 + 2 * l4]     = f2tf(sacc[nf][0]);
                p0[nf * 8 + 2 * l4 + 1] = f2tf(sacc[nf][1]);
                p1[nf * 8 + 2 * l4]     = f2tf(sacc[nf][2]);
                p1[nf * 8 + 2 * l4 + 1] = f2tf(sacc[nf][3]);
            }
        }
        __syncwarp();

        // O += P @ V
#pragma unroll
        for (int ks = 0; ks < 4; ks++) {
            unsigned pa[4];
            const unsigned* p0 = Pm[w] + g * PSTRIDE;
            const unsigned* p1 = Pm[w] + (g + 8) * PSTRIDE;
            pa[0] = p0[ks * 8 + l4];
            pa[1] = p1[ks * 8 + l4];
            pa[2] = p0[ks * 8 + l4 + 4];
            pa[3] = p1[ks * 8 + l4 + 4];
            const float* v0 = Vb + (ks * 8 + l4) * VFS;
            const float* v1 = Vb + (ks * 8 + l4 + 4) * VFS;
#pragma unroll
            for (int nf = 0; nf < 8; nf++) {
                unsigned b[2];
                b[0] = __float_as_uint(v0[nf * 8 + g]);
                b[1] = __float_as_uint(v1[nf * 8 + g]);
                mma_tf32(oacc[nf], pa, b);
            }
        }

        __syncthreads();
        if (t + 2 < NT) stage2(t + 2, t & 1);
        CP_COMMIT();
    }

    // Epilogue: normalize, RN-round, write [B,N,H*D]
    float il0 = 1.0f / l0, il1 = 1.0f / l1;
    size_t base0 = ((size_t)bb * SEQ + (qbase + g)) * EMB + h * HDIM;
    size_t base1 = base0 + (size_t)8 * EMB;
#pragma unroll
    for (int nf = 0; nf < 8; nf++) {
        int col = nf * 8 + 2 * l4;
        g_attn[base0 + col]     = f2tff(oacc[nf][0] * il0);
        g_attn[base0 + col + 1] = f2tff(oacc[nf][1] * il0);
        g_attn[base1 + col]     = f2tff(oacc[nf][2] * il1);
        g_attn[base1 + col + 1] = f2tff(oacc[nf][3] * il1);
    }
}

// ---------------------------------------------------------------------------
// Launch
// ---------------------------------------------------------------------------
extern "C" void kernel_launch(void* const* d_in, const int* in_sizes, int n_in,
                              void* d_out, int out_size)
{
    const float* x     = (const float*)d_in[0];
    const float* qkv_w = (const float*)d_in[1];
    const float* qkv_b = (const float*)d_in[2];
    const float* out_w = (const float*)d_in[3];
    const float* out_b = (const float*)d_in[4];
    float* out = (float*)d_out;

    float* dx; float* dwq; float* dwo;
    cudaGetSymbolAddress((void**)&dx,  g_x);
    cudaGetSymbolAddress((void**)&dwq, g_wqkv);
    cudaGetSymbolAddress((void**)&dwo, g_wout);

    // Pre-round inputs to tf32 (RN) so GEMM raw-bit operands are RN-exact
    cvt_tf32_kernel<<<2048, 256>>>((const float4*)x,     (float4*)dx,  ROWS * EMB / 4);
    cvt_tf32_kernel<<<1024, 256>>>((const float4*)qkv_w, (float4*)dwq, QKVN * EMB / 4);
    cvt_tf32_kernel<<<512,  256>>>((const float4*)out_w, (float4*)dwo, EMB * EMB / 4);

    dim3 g1(ROWS / 128, QKVN / 128);     // 64 x 24
    qkv_gemm_kernel<<<g1, 128>>>(qkv_b);

    dim3 g2(SEQ / 64, HEADS, BATCH);     // 32 x 16 x 4
    attn_kernel<<<g2, 128>>>();

    dim3 g3(ROWS / 128, EMB / 128);      // 64 x 8
    proj_gemm_kernel<<<g3, 128>>>(out_b, out);
}

// round 10
// speedup vs baseline: 3.6970x; 1.0210x over previous
#include <cuda_runtime.h>
#include <cuda_bf16.h>
#include <cstdint>
#include <math.h>

// Problem constants
#define BATCH 4
#define SEQ   2048
#define EMB   1024
#define HEADS 16
#define HDIM  64
#define QKVN  (3 * EMB)          // 3072
#define ROWS  (BATCH * SEQ)      // 8192

// ---------------------------------------------------------------------------
// Scratch — pre-rounded inputs, head-major Q/K/V, attention output.
// Everything here is RN-rounded to tf32 so raw-bit tf32 operands are RN-exact.
// ---------------------------------------------------------------------------
__device__ float g_x   [ROWS * EMB];
__device__ float g_wqkv[QKVN * EMB];
__device__ float g_wout[EMB * EMB];
__device__ float g_q[BATCH * HEADS * SEQ * HDIM];
__device__ float g_k[BATCH * HEADS * SEQ * HDIM];
__device__ float g_v[BATCH * HEADS * SEQ * HDIM];
__device__ float g_attn[ROWS * EMB];

// ---------------------------------------------------------------------------
// Helpers
// ---------------------------------------------------------------------------
__device__ __forceinline__ unsigned f2tf(float f) {
    unsigned u;
    asm("cvt.rna.tf32.f32 %0, %1;" : "=r"(u) : "f"(f));
    return u;
}
__device__ __forceinline__ float f2tff(float f) { return __uint_as_float(f2tf(f)); }

__device__ __forceinline__ float fex2(float x) {
    float r;
    asm("ex2.approx.f32 %0, %1;" : "=f"(r) : "f"(x));
    return r;
}

__device__ __forceinline__ void mma_tf32(float d[4], const unsigned a[4],
                                         const unsigned b[2]) {
    asm volatile(
        "mma.sync.aligned.m16n8k8.row.col.f32.tf32.tf32.f32 "
        "{%0,%1,%2,%3}, {%4,%5,%6,%7}, {%8,%9}, {%0,%1,%2,%3};"
        : "+f"(d[0]), "+f"(d[1]), "+f"(d[2]), "+f"(d[3])
        : "r"(a[0]), "r"(a[1]), "r"(a[2]), "r"(a[3]),
          "r"(b[0]), "r"(b[1]));
}

__device__ __forceinline__ void cp16(void* smem_dst, const void* gmem_src) {
    unsigned s = (unsigned)__cvta_generic_to_shared(smem_dst);
    asm volatile("cp.async.cg.shared.global [%0], [%1], 16;"
                 :: "r"(s), "l"(gmem_src));
}
#define CP_COMMIT() asm volatile("cp.async.commit_group;" ::: "memory")
#define CP_WAIT1()  asm volatile("cp.async.wait_group 1;"  ::: "memory")

// ---------------------------------------------------------------------------
// Pre-kernel: RN-round buffers to tf32
// ---------------------------------------------------------------------------
__global__ __launch_bounds__(256) void cvt_tf32_kernel(
    const float4* __restrict__ src, float4* __restrict__ dst, int n4)
{
    int i = blockIdx.x * blockDim.x + threadIdx.x;
    int stride = gridDim.x * blockDim.x;
    for (; i < n4; i += stride) {
        float4 v = src[i];
        v.x = f2tff(v.x); v.y = f2tff(v.y);
        v.z = f2tff(v.z); v.w = f2tff(v.w);
        dst[i] = v;
    }
}

// ---------------------------------------------------------------------------
// GEMM mainloop: C[128x128] = A[m0..,1024] x B[j0..,1024]^T, both row-major
// K-contiguous, pre-rounded tf32. 256 threads = 8 warps (4x2), warp tile
// 32x64 -> 64 acc regs/thread (2 CTAs/SM, 16 warps/SM).
// acc[mi][nf][slot]: rows wm*32+mi*16+{g,g+8}, cols wn*64+nf*8+2*l4+{0,1}
// ---------------------------------------------------------------------------
#define SPAD 20
#define STAGE (128 * SPAD)

__device__ __forceinline__ void gemm_mainloop(
    const float* __restrict__ Ag, const float* __restrict__ Bg,
    int m0, int j0, float* As, float* Bs, float acc[2][8][4])
{
    const int tid  = threadIdx.x;
    const int lane = tid & 31;
    const int w    = tid >> 5;
    const int g    = lane >> 2;
    const int l4   = lane & 3;
    const int wm   = w >> 1;     // 0..3
    const int wn   = w & 1;      // 0..1

#pragma unroll
    for (int mi = 0; mi < 2; mi++)
#pragma unroll
        for (int nf = 0; nf < 8; nf++)
#pragma unroll
            for (int s = 0; s < 4; s++) acc[mi][nf][s] = 0.0f;

    auto stage = [&](int slab, int buf) {
        const int k0 = slab * 16;
        float* Ad = As + buf * STAGE;
        float* Bd = Bs + buf * STAGE;
#pragma unroll
        for (int it = 0; it < 2; it++) {
            int e   = it * 256 + tid;    // 0..511
            int row = e >> 2;            // 0..127
            int c4  = (e & 3) * 4;
            cp16(Ad + row * SPAD + c4, Ag + (size_t)(m0 + row) * EMB + k0 + c4);
            cp16(Bd + row * SPAD + c4, Bg + (size_t)(j0 + row) * EMB + k0 + c4);
        }
    };

    stage(0, 0); CP_COMMIT();
    stage(1, 1); CP_COMMIT();

    for (int s = 0; s < 64; s++) {
        CP_WAIT1();
        __syncthreads();
        const float* Ab = As + (s & 1) * STAGE;
        const float* Bb = Bs + (s & 1) * STAGE;

#pragma unroll
        for (int ks = 0; ks < 2; ks++) {
            const int kk = ks * 8;
            unsigned a[2][4];
#pragma unroll
            for (int mi = 0; mi < 2; mi++) {
                int mr = wm * 32 + mi * 16 + g;
                a[mi][0] = __float_as_uint(Ab[mr * SPAD + kk + l4]);
                a[mi][1] = __float_as_uint(Ab[(mr + 8) * SPAD + kk + l4]);
                a[mi][2] = __float_as_uint(Ab[mr * SPAD + kk + l4 + 4]);
                a[mi][3] = __float_as_uint(Ab[(mr + 8) * SPAD + kk + l4 + 4]);
            }
#pragma unroll
            for (int nf = 0; nf < 8; nf++) {
                int nr = wn * 64 + nf * 8 + g;
                unsigned b[2];
                b[0] = __float_as_uint(Bb[nr * SPAD + kk + l4]);
                b[1] = __float_as_uint(Bb[nr * SPAD + kk + l4 + 4]);
                mma_tf32(acc[0][nf], a[0], b);
                mma_tf32(acc[1][nf], a[1], b);
            }
        }
        __syncthreads();
        if (s + 2 < 64) stage(s + 2, s & 1);
        CP_COMMIT();
    }
}

// ---------------------------------------------------------------------------
// Kernel 1: QKV GEMM + scatter into head-major g_q/g_k/g_v (tf32-rounded)
// ---------------------------------------------------------------------------
__global__ __launch_bounds__(256, 2) void qkv_gemm_kernel(
    const float* __restrict__ bias)
{
    __shared__ __align__(16) float As[2 * STAGE];
    __shared__ __align__(16) float Bs[2 * STAGE];
    float acc[2][8][4];
    const int m0 = blockIdx.x * 128;
    const int j0 = blockIdx.y * 128;
    gemm_mainloop(g_x, g_wqkv, m0, j0, As, Bs, acc);

    const int lane = threadIdx.x & 31;
    const int wrp  = threadIdx.x >> 5;
    const int g = lane >> 2, l4 = lane & 3;
    const int wm = wrp >> 1, wn = wrp & 1;

#pragma unroll
    for (int mi = 0; mi < 2; mi++)
#pragma unroll
        for (int rr = 0; rr < 2; rr++) {
            int m = m0 + wm * 32 + mi * 16 + g + rr * 8;
            int b = m >> 11;
            int n = m & (SEQ - 1);
#pragma unroll
            for (int nf = 0; nf < 8; nf++)
#pragma unroll
                for (int cc = 0; cc < 2; cc++) {
                    int jj = j0 + wn * 64 + nf * 8 + 2 * l4 + cc;
                    float v = f2tff(acc[mi][nf][rr * 2 + cc] + bias[jj]);
                    int which = jj >> 10;
                    int rem = jj & 1023;
                    int h = rem >> 6, d = rem & 63;
                    float* dst = (which == 0) ? g_q : (which == 1) ? g_k : g_v;
                    dst[((((size_t)b * HEADS + h) * SEQ) + n) * HDIM + d] = v;
                }
        }
}

// ---------------------------------------------------------------------------
// Kernel 3: out-proj GEMM (final output full fp32)
// ---------------------------------------------------------------------------
__global__ __launch_bounds__(256, 2) void proj_gemm_kernel(
    const float* __restrict__ bias,
    float* __restrict__ out)
{
    __shared__ __align__(16) float As[2 * STAGE];
    __shared__ __align__(16) float Bs[2 * STAGE];
    float acc[2][8][4];
    const int m0 = blockIdx.x * 128;
    const int j0 = blockIdx.y * 128;
    gemm_mainloop(g_attn, g_wout, m0, j0, As, Bs, acc);

    const int lane = threadIdx.x & 31;
    const int wrp  = threadIdx.x >> 5;
    const int g = lane >> 2, l4 = lane & 3;
    const int wm = wrp >> 1, wn = wrp & 1;

#pragma unroll
    for (int mi = 0; mi < 2; mi++)
#pragma unroll
        for (int rr = 0; rr < 2; rr++) {
            size_t m = m0 + wm * 32 + mi * 16 + g + rr * 8;
#pragma unroll
            for (int nf = 0; nf < 8; nf++)
#pragma unroll
                for (int cc = 0; cc < 2; cc++) {
                    int jj = j0 + wn * 64 + nf * 8 + 2 * l4 + cc;
                    out[m * EMB + jj] = acc[mi][nf][rr * 2 + cc] + bias[jj];
                }
        }
}

// ---------------------------------------------------------------------------
// Kernel 2: flash attention, tf32 mma.sync, cp.async double-buffered K/V.
// 256 threads (8 warps), 128-query tile; warp w owns q rows q0+w*16..+16.
// Halves K/V global/L2 traffic vs 64-query CTAs. Per-warp structure is
// identical to the R7 version. 54.3KB dynamic smem.
// ---------------------------------------------------------------------------
#define KT2     32
#define KFS     68
#define VFS     72
#define PSTRIDE 36
#define ATTN_SMEM_BYTES ((2*KT2*KFS + 2*KT2*VFS + 8*16*PSTRIDE) * 4)

__global__ __launch_bounds__(256, 2) void attn_kernel()
{
    extern __shared__ __align__(16) float dsm[];
    float* Kf = dsm;                          // 2*KT2*KFS
    float* Vf = Kf + 2 * KT2 * KFS;           // 2*KT2*VFS
    unsigned* Pm = (unsigned*)(Vf + 2 * KT2 * VFS);  // 8 warps * 16 * PSTRIDE

    const int tid  = threadIdx.x;
    const int lane = tid & 31;
    const int w    = tid >> 5;       // 0..7
    const int g    = lane >> 2;
    const int l4   = lane & 3;
    const int q0   = blockIdx.x * 128;
    const int h    = blockIdx.y;
    const int bb   = blockIdx.z;

    const size_t head_off = (((size_t)bb * HEADS + h) * SEQ) * HDIM;
    const float* qg = g_q + head_off;
    const float* kg = g_k + head_off;
    const float* vg = g_v + head_off;

    const float QSCALE = 0.125f * 1.4426950408889634f;
    const int qbase = q0 + w * 16;
    unsigned qa[8][4];
    {
        const float* qr0 = qg + (size_t)(qbase + g) * HDIM;
        const float* qr1 = qg + (size_t)(qbase + g + 8) * HDIM;
#pragma unroll
        for (int kf = 0; kf < 8; kf++) {
            qa[kf][0] = f2tf(qr0[kf * 8 + l4] * QSCALE);
            qa[kf][1] = f2tf(qr1[kf * 8 + l4] * QSCALE);
            qa[kf][2] = f2tf(qr0[kf * 8 + l4 + 4] * QSCALE);
            qa[kf][3] = f2tf(qr1[kf * 8 + l4 + 4] * QSCALE);
        }
    }

    auto stage2 = [&](int t, int buf) {
        const int kt = t * KT2;
        float* Kd = Kf + buf * KT2 * KFS;
        float* Vd = Vf + buf * KT2 * VFS;
        // K tile: 32 rows x 64 cols = 512 float4 over 256 threads
#pragma unroll
        for (int it = 0; it < 2; it++) {
            int e   = it * 256 + tid;
            int row = e >> 4;
            int c4  = (e & 15) * 4;
            cp16(Kd + row * KFS + c4, kg + (size_t)(kt + row) * HDIM + c4);
        }
#pragma unroll
        for (int it = 0; it < 2; it++) {
            int e   = it * 256 + tid;
            int row = e >> 4;
            int c4  = (e & 15) * 4;
            cp16(Vd + row * VFS + c4, vg + (size_t)(kt + row) * HDIM + c4);
        }
    };

    float oacc[8][4];
#pragma unroll
    for (int nf = 0; nf < 8; nf++)
#pragma unroll
        for (int s = 0; s < 4; s++) oacc[nf][s] = 0.0f;
    float mx0 = -1e30f, mx1 = -1e30f, l0 = 0.0f, l1 = 0.0f;

    stage2(0, 0); CP_COMMIT();
    stage2(1, 1); CP_COMMIT();

    const int NT = SEQ / KT2;    // 64 tiles
    for (int t = 0; t < NT; t++) {
        CP_WAIT1();
        __syncthreads();
        const float* Kb = Kf + (t & 1) * KT2 * KFS;
        const float* Vb = Vf + (t & 1) * KT2 * VFS;

        // S = Qs @ K^T : warp computes 16 x 32
        float sacc[4][4];
#pragma unroll
        for (int nf = 0; nf < 4; nf++)
#pragma unroll
            for (int s = 0; s < 4; s++) sacc[nf][s] = 0.0f;

#pragma unroll
        for (int nf = 0; nf < 4; nf++) {
            const float* kr = Kb + (nf * 8 + g) * KFS;
#pragma unroll
            for (int kf = 0; kf < 8; kf++) {
                unsigned b[2];
                b[0] = __float_as_uint(kr[kf * 8 + l4]);
                b[1] = __float_as_uint(kr[kf * 8 + l4 + 4]);
                mma_tf32(sacc[nf], qa[kf], b);
            }
        }

        // Online softmax (exp2 domain), rows g and g+8
        float tm0 = -1e30f, tm1 = -1e30f;
#pragma unroll
        for (int nf = 0; nf < 4; nf++) {
            tm0 = fmaxf(tm0, fmaxf(sacc[nf][0], sacc[nf][1]));
            tm1 = fmaxf(tm1, fmaxf(sacc[nf][2], sacc[nf][3]));
        }
        tm0 = fmaxf(tm0, __shfl_xor_sync(0xffffffffu, tm0, 1));
        tm0 = fmaxf(tm0, __shfl_xor_sync(0xffffffffu, tm0, 2));
        tm1 = fmaxf(tm1, __shfl_xor_sync(0xffffffffu, tm1, 1));
        tm1 = fmaxf(tm1, __shfl_xor_sync(0xffffffffu, tm1, 2));

        float nm0 = fmaxf(mx0, tm0), nm1 = fmaxf(mx1, tm1);
        float c0 = fex2(mx0 - nm0), c1 = fex2(mx1 - nm1);
        mx0 = nm0; mx1 = nm1;

        float rs0 = 0.0f, rs1 = 0.0f;
#pragma unroll
        for (int nf = 0; nf < 4; nf++) {
            sacc[nf][0] = fex2(sacc[nf][0] - nm0); rs0 += sacc[nf][0];
            sacc[nf][1] = fex2(sacc[nf][1] - nm0); rs0 += sacc[nf][1];
            sacc[nf][2] = fex2(sacc[nf][2] - nm1); rs1 += sacc[nf][2];
            sacc[nf][3] = fex2(sacc[nf][3] - nm1); rs1 += sacc[nf][3];
        }
        rs0 += __shfl_xor_sync(0xffffffffu, rs0, 1);
        rs0 += __shfl_xor_sync(0xffffffffu, rs0, 2);
        rs1 += __shfl_xor_sync(0xffffffffu, rs1, 1);
        rs1 += __shfl_xor_sync(0xffffffffu, rs1, 2);
        l0 = l0 * c0 + rs0;
        l1 = l1 * c1 + rs1;
#pragma unroll
        for (int nf = 0; nf < 8; nf++) {
            oacc[nf][0] *= c0; oacc[nf][1] *= c0;
            oacc[nf][2] *= c1; oacc[nf][3] *= c1;
        }

        // P RN-rounded into warp-private buffer (only __syncwarp needed)
        {
            unsigned* p0 = Pm + (w * 16 + g) * PSTRIDE;
            unsigned* p1 = Pm + (w * 16 + g + 8) * PSTRIDE;
#pragma unroll
            for (int nf = 0; nf < 4; nf++) {
                p0[nf * 8 + 2 * l4]     = f2tf(sacc[nf][0]);
                p0[nf * 8 + 2 * l4 + 1] = f2tf(sacc[nf][1]);
                p1[nf * 8 + 2 * l4]     = f2tf(sacc[nf][2]);
                p1[nf * 8 + 2 * l4 + 1] = f2tf(sacc[nf][3]);
            }
        }
        __syncwarp();

        // O += P @ V
#pragma unroll
        for (int ks = 0; ks < 4; ks++) {
            unsigned pa[4];
            const unsigned* p0 = Pm + (w * 16 + g) * PSTRIDE;
            const unsigned* p1 = Pm + (w * 16 + g + 8) * PSTRIDE;
            pa[0] = p0[ks * 8 + l4];
            pa[1] = p1[ks * 8 + l4];
            pa[2] = p0[ks * 8 + l4 + 4];
            pa[3] = p1[ks * 8 + l4 + 4];
            const float* v0 = Vb + (ks * 8 + l4) * VFS;
            const float* v1 = Vb + (ks * 8 + l4 + 4) * VFS;
#pragma unroll
            for (int nf = 0; nf < 8; nf++) {
                unsigned b[2];
                b[0] = __float_as_uint(v0[nf * 8 + g]);
                b[1] = __float_as_uint(v1[nf * 8 + g]);
                mma_tf32(oacc[nf], pa, b);
            }
        }

        __syncthreads();
        if (t + 2 < NT) stage2(t + 2, t & 1);
        CP_COMMIT();
    }

    // Epilogue: normalize, RN-round, write [B,N,H*D]
    float il0 = 1.0f / l0, il1 = 1.0f / l1;
    size_t base0 = ((size_t)bb * SEQ + (qbase + g)) * EMB + h * HDIM;
    size_t base1 = base0 + (size_t)8 * EMB;
#pragma unroll
    for (int nf = 0; nf < 8; nf++) {
        int col = nf * 8 + 2 * l4;
        g_attn[base0 + col]     = f2tff(oacc[nf][0] * il0);
        g_attn[base0 + col + 1] = f2tff(oacc[nf][1] * il0);
        g_attn[base1 + col]     = f2tff(oacc[nf][2] * il1);
        g_attn[base1 + col + 1] = f2tff(oacc[nf][3] * il1);
    }
}

// ---------------------------------------------------------------------------
// Launch
// ---------------------------------------------------------------------------
extern "C" void kernel_launch(void* const* d_in, const int* in_sizes, int n_in,
                              void* d_out, int out_size)
{
    const float* x     = (const float*)d_in[0];
    const float* qkv_w = (const float*)d_in[1];
    const float* qkv_b = (const float*)d_in[2];
    const float* out_w = (const float*)d_in[3];
    const float* out_b = (const float*)d_in[4];
    float* out = (float*)d_out;

    float* dx; float* dwq; float* dwo;
    cudaGetSymbolAddress((void**)&dx,  g_x);
    cudaGetSymbolAddress((void**)&dwq, g_wqkv);
    cudaGetSymbolAddress((void**)&dwo, g_wout);

    cudaFuncSetAttribute(attn_kernel,
                         cudaFuncAttributeMaxDynamicSharedMemorySize,
                         ATTN_SMEM_BYTES);

    cvt_tf32_kernel<<<2048, 256>>>((const float4*)x,     (float4*)dx,  ROWS * EMB / 4);
    cvt_tf32_kernel<<<1024, 256>>>((const float4*)qkv_w, (float4*)dwq, QKVN * EMB / 4);
    cvt_tf32_kernel<<<512,  256>>>((const float4*)out_w, (float4*)dwo, EMB * EMB / 4);

    dim3 g1(ROWS / 128, QKVN / 128);     // 64 x 24
    qkv_gemm_kernel<<<g1, 256>>>(qkv_b);

    dim3 g2(SEQ / 128, HEADS, BATCH);    // 16 x 16 x 4
    attn_kernel<<<g2, 256, ATTN_SMEM_BYTES>>>();

    dim3 g3(ROWS / 128, EMB / 128);      // 64 x 8
    proj_gemm_kernel<<<g3, 256>>>(out_b, out);
}